// round 2
// baseline (speedup 1.0000x reference)
#include <cuda_runtime.h>

// LightGCN 3-layer propagation, N=200000 nodes, E=3.2M edges, D=64+64 fused.
// Strategy: build CSR-by-dst per launch (graph-replay safe: all scratch
// re-initialized each call), then gather-based propagation (warp-per-node,
// 32 lanes x float4 = 128-float fused row). Avoids 1.2B fp32 atomics.

#define USER_NUM 100000
#define N_NODES  200000
#define NE       3200000
#define DV       32          // float4 per fused row (128 floats)

__device__ int   g_cnt[N_NODES];
__device__ int   g_cursor[N_NODES];
__device__ int   g_rowptr[N_NODES + 1];
__device__ float g_dis[N_NODES];
__device__ int   g_csr_src[NE];
__device__ float g_csr_norm[NE];
__device__ float g_emb0[(size_t)N_NODES * 128];
__device__ float g_emb1[(size_t)N_NODES * 128];
__device__ float g_acc [(size_t)N_NODES * 128];

// ---------------------------------------------------------------------------
__global__ void k_zero() {
    int i = blockIdx.x * blockDim.x + threadIdx.x;
    int stride = gridDim.x * blockDim.x;
    for (; i < N_NODES; i += stride) {
        g_cnt[i] = 0;
        g_cursor[i] = 0;
    }
}

__global__ void k_count(const int* __restrict__ dst) {
    int i = blockIdx.x * blockDim.x + threadIdx.x;
    int stride = gridDim.x * blockDim.x;
    for (; i < NE; i += stride) {
        atomicAdd(&g_cnt[dst[i]], 1);
    }
}

// Single-block exclusive scan over g_cnt -> g_rowptr; also computes g_dis.
__global__ void k_scan() {
    __shared__ int sums[1024];
    const int t = threadIdx.x;
    const int CH = (N_NODES + 1023) / 1024;   // 196
    int beg = t * CH;
    int end = beg + CH; if (end > N_NODES) end = N_NODES;

    int s = 0;
    for (int i = beg; i < end; i++) {
        int c = g_cnt[i];
        s += c;
        g_dis[i] = (c > 0) ? rsqrtf((float)c) : 0.0f;
    }
    sums[t] = s;
    __syncthreads();

    // Hillis-Steele inclusive scan over 1024 partials
    for (int off = 1; off < 1024; off <<= 1) {
        int v = 0;
        if (t >= off) v = sums[t - off];
        __syncthreads();
        sums[t] += v;
        __syncthreads();
    }

    int run = (t == 0) ? 0 : sums[t - 1];   // exclusive base
    for (int i = beg; i < end; i++) {
        g_rowptr[i] = run;
        run += g_cnt[i];
    }
    if (t == 1023) g_rowptr[N_NODES] = run;  // == NE
}

__global__ void k_scatter(const int* __restrict__ src, const int* __restrict__ dst) {
    int i = blockIdx.x * blockDim.x + threadIdx.x;
    int stride = gridDim.x * blockDim.x;
    for (; i < NE; i += stride) {
        int s = src[i];
        int d = dst[i];
        int pos = g_rowptr[d] + atomicAdd(&g_cursor[d], 1);
        g_csr_src[pos]  = s;
        g_csr_norm[pos] = g_dis[s] * g_dis[d];
    }
}

// Pack 4 inputs into fused [N,128] layout; also initialize acc = emb0.
__global__ void k_pack(const float4* __restrict__ ui, const float4* __restrict__ ii,
                       const float4* __restrict__ ug, const float4* __restrict__ ig) {
    int idx = blockIdx.x * blockDim.x + threadIdx.x;
    int stride = gridDim.x * blockDim.x;
    float4* e0 = reinterpret_cast<float4*>(g_emb0);
    float4* ac = reinterpret_cast<float4*>(g_acc);
    const int total = N_NODES * DV;
    for (; idx < total; idx += stride) {
        int node = idx >> 5;
        int q    = idx & 31;
        float4 v;
        if (q < 16) {
            v = (node < USER_NUM) ? ui[node * 16 + q]
                                  : ii[(node - USER_NUM) * 16 + q];
        } else {
            int qq = q - 16;
            v = (node < USER_NUM) ? ug[node * 16 + qq]
                                  : ig[(node - USER_NUM) * 16 + qq];
        }
        e0[idx] = v;
        ac[idx] = v;
    }
}

// Warp-per-node gather propagation. in/out selected by flag; acc += result.
__global__ void __launch_bounds__(256) k_prop(int in_is_0, int write_next) {
    int gtid = blockIdx.x * blockDim.x + threadIdx.x;
    int node = gtid >> 5;
    if (node >= N_NODES) return;
    int lane = threadIdx.x & 31;

    const float4* __restrict__ xin =
        reinterpret_cast<const float4*>(in_is_0 ? g_emb0 : g_emb1);
    float4* xout = reinterpret_cast<float4*>(in_is_0 ? g_emb1 : g_emb0);
    float4* accp = reinterpret_cast<float4*>(g_acc);

    int beg = __ldg(&g_rowptr[node]);
    int end = __ldg(&g_rowptr[node + 1]);

    float4 a = make_float4(0.f, 0.f, 0.f, 0.f);
    int i = beg;
    // 4-way unroll for memory-level parallelism on the L2 gathers
    for (; i + 4 <= end; i += 4) {
        int   s0 = __ldg(&g_csr_src[i + 0]), s1 = __ldg(&g_csr_src[i + 1]);
        int   s2 = __ldg(&g_csr_src[i + 2]), s3 = __ldg(&g_csr_src[i + 3]);
        float w0 = __ldg(&g_csr_norm[i + 0]), w1 = __ldg(&g_csr_norm[i + 1]);
        float w2 = __ldg(&g_csr_norm[i + 2]), w3 = __ldg(&g_csr_norm[i + 3]);
        float4 v0 = xin[s0 * DV + lane];
        float4 v1 = xin[s1 * DV + lane];
        float4 v2 = xin[s2 * DV + lane];
        float4 v3 = xin[s3 * DV + lane];
        a.x += w0 * v0.x + w1 * v1.x + w2 * v2.x + w3 * v3.x;
        a.y += w0 * v0.y + w1 * v1.y + w2 * v2.y + w3 * v3.y;
        a.z += w0 * v0.z + w1 * v1.z + w2 * v2.z + w3 * v3.z;
        a.w += w0 * v0.w + w1 * v1.w + w2 * v2.w + w3 * v3.w;
    }
    for (; i < end; ++i) {
        int   s = __ldg(&g_csr_src[i]);
        float w = __ldg(&g_csr_norm[i]);
        float4 v = xin[s * DV + lane];
        a.x += w * v.x; a.y += w * v.y; a.z += w * v.z; a.w += w * v.w;
    }

    int o = node * DV + lane;
    float4 ac = accp[o];
    ac.x += a.x; ac.y += a.y; ac.z += a.z; ac.w += a.w;
    accp[o] = ac;
    if (write_next) xout[o] = a;
}

// Final: split fused acc back into [int | geo] sections, scale by 1/16.
__global__ void k_out(float4* __restrict__ out) {
    int idx = blockIdx.x * blockDim.x + threadIdx.x;
    int stride = gridDim.x * blockDim.x;
    const float4* accp = reinterpret_cast<const float4*>(g_acc);
    const float scale = 1.0f / 16.0f;
    const int total = N_NODES * DV;
    const int geo_base = N_NODES * 16;  // in float4 units
    for (; idx < total; idx += stride) {
        int node = idx >> 5;
        int q    = idx & 31;
        float4 v = accp[idx];
        v.x *= scale; v.y *= scale; v.z *= scale; v.w *= scale;
        if (q < 16) out[node * 16 + q] = v;
        else        out[geo_base + node * 16 + (q - 16)] = v;
    }
}

// ---------------------------------------------------------------------------
extern "C" void kernel_launch(void* const* d_in, const int* in_sizes, int n_in,
                              void* d_out, int out_size) {
    const float4* user_int = (const float4*)d_in[0];
    const float4* item_int = (const float4*)d_in[1];
    const float4* user_geo = (const float4*)d_in[2];
    const float4* item_geo = (const float4*)d_in[3];
    const int*    edge     = (const int*)d_in[4];
    const int* src = edge;        // row 0 of [2, E]
    const int* dst = edge + NE;   // row 1

    float4* out = (float4*)d_out;

    const int TB = 256;
    const int prop_blocks = (N_NODES * 32 + TB - 1) / TB;   // 25000
    const int flat_blocks = (N_NODES * DV + TB - 1) / TB;   // 25000

    k_zero<<<512, TB>>>();
    k_count<<<4096, TB>>>(dst);
    k_scan<<<1, 1024>>>();
    k_scatter<<<4096, TB>>>(src, dst);
    k_pack<<<flat_blocks, TB>>>(user_int, item_int, user_geo, item_geo);

    // layer 1: emb0 -> emb1 ; layer 2: emb1 -> emb0 ; layer 3: emb0 -> (acc only)
    k_prop<<<prop_blocks, TB>>>(1, 1);
    k_prop<<<prop_blocks, TB>>>(0, 1);
    k_prop<<<prop_blocks, TB>>>(1, 0);

    k_out<<<flat_blocks, TB>>>(out);
}

// round 4
// speedup vs baseline: 1.3550x; 1.3550x over previous
#include <cuda_runtime.h>
#include <cuda_fp16.h>

// LightGCN 3-layer propagation, N=200000, E=3.2M, D=64+64 fused to 128.
// CSR-by-dst rebuilt per launch (graph-replay safe). Gather propagation:
// warp-per-node, lane handles 4 fused cols. Intermediate embeddings in fp16
// (256B/row) to halve L2 gather traffic; accumulation fp32 in registers.
// Final sum (e0+e1+e2+e3)/16 fused into the layer-3 kernel, e0 read from
// the original fp32 inputs.
// NOTE: __device__ globals are referenced ONLY from device code (host code
// passing a __device__ symbol as a kernel arg resolves to the host shadow —
// that bug tripped the R3 allocation guard via ATS page migration).

#define USER_NUM 100000
#define N_NODES  200000
#define NE       3200000

__device__ int   g_cnt[N_NODES];
__device__ int   g_cursor[N_NODES];
__device__ int   g_rowptr[N_NODES + 1];
__device__ float g_dis[N_NODES];
__device__ int2  g_csr[NE];                        // (src, norm-bits)
__device__ uint2 g_e0h[(size_t)N_NODES * 32];      // fp16 rows, 256B each
__device__ uint2 g_e1h[(size_t)N_NODES * 32];
__device__ uint2 g_e2h[(size_t)N_NODES * 32];

// ---- fp16 <-> fp32 row-chunk helpers (4 floats <-> uint2) ------------------
__device__ __forceinline__ uint2 f4_to_h(float4 v) {
    __half2 lo = __floats2half2_rn(v.x, v.y);
    __half2 hi = __floats2half2_rn(v.z, v.w);
    uint2 u;
    u.x = *reinterpret_cast<unsigned*>(&lo);
    u.y = *reinterpret_cast<unsigned*>(&hi);
    return u;
}
__device__ __forceinline__ float4 h_to_f4(uint2 u) {
    __half2 lo = *reinterpret_cast<__half2*>(&u.x);
    __half2 hi = *reinterpret_cast<__half2*>(&u.y);
    float2 a = __half22float2(lo);
    float2 b = __half22float2(hi);
    return make_float4(a.x, a.y, b.x, b.y);
}

// ---------------------------------------------------------------------------
__global__ void k_zero() {
    int i = blockIdx.x * blockDim.x + threadIdx.x;
    int stride = gridDim.x * blockDim.x;
    for (; i < N_NODES; i += stride) {
        g_cnt[i] = 0;
        g_cursor[i] = 0;
    }
}

__global__ void k_count(const int* __restrict__ dst) {
    int i = blockIdx.x * blockDim.x + threadIdx.x;
    int stride = gridDim.x * blockDim.x;
    for (; i < NE; i += stride) {
        atomicAdd(&g_cnt[dst[i]], 1);
    }
}

// Single-block exclusive scan over g_cnt -> g_rowptr; also computes g_dis.
__global__ void k_scan() {
    __shared__ int sums[1024];
    const int t = threadIdx.x;
    const int CH = (N_NODES + 1023) / 1024;   // 196
    int beg = t * CH;
    int end = beg + CH; if (end > N_NODES) end = N_NODES;

    int s = 0;
    for (int i = beg; i < end; i++) {
        int c = g_cnt[i];
        s += c;
        g_dis[i] = (c > 0) ? rsqrtf((float)c) : 0.0f;
    }
    sums[t] = s;
    __syncthreads();

    for (int off = 1; off < 1024; off <<= 1) {
        int v = 0;
        if (t >= off) v = sums[t - off];
        __syncthreads();
        sums[t] += v;
        __syncthreads();
    }

    int run = (t == 0) ? 0 : sums[t - 1];
    for (int i = beg; i < end; i++) {
        g_rowptr[i] = run;
        run += g_cnt[i];
    }
    if (t == 1023) g_rowptr[N_NODES] = run;
}

__global__ void k_scatter(const int* __restrict__ src, const int* __restrict__ dst) {
    int i = blockIdx.x * blockDim.x + threadIdx.x;
    int stride = gridDim.x * blockDim.x;
    for (; i < NE; i += stride) {
        int s = src[i];
        int d = dst[i];
        int pos = g_rowptr[d] + atomicAdd(&g_cursor[d], 1);
        float w = g_dis[s] * g_dis[d];
        g_csr[pos] = make_int2(s, __float_as_int(w));
    }
}

// Per-lane float4 chunk of the fused 128-col row, from the original inputs.
__device__ __forceinline__ float4 load_input_chunk(
    const float4* __restrict__ ui, const float4* __restrict__ ii,
    const float4* __restrict__ ug, const float4* __restrict__ ig,
    int node, int lane)
{
    if (lane < 16) {
        return (node < USER_NUM) ? ui[node * 16 + lane]
                                 : ii[(node - USER_NUM) * 16 + lane];
    } else {
        int q = lane - 16;
        return (node < USER_NUM) ? ug[node * 16 + q]
                                 : ig[(node - USER_NUM) * 16 + q];
    }
}

// Pack inputs into fused fp16 rows (e0h).
__global__ void k_pack(const float4* __restrict__ ui, const float4* __restrict__ ii,
                       const float4* __restrict__ ug, const float4* __restrict__ ig) {
    int idx = blockIdx.x * blockDim.x + threadIdx.x;
    int stride = gridDim.x * blockDim.x;
    const int total = N_NODES * 32;
    for (; idx < total; idx += stride) {
        int node = idx >> 5;
        int lane = idx & 31;
        g_e0h[idx] = f4_to_h(load_input_chunk(ui, ii, ug, ig, node, lane));
    }
}

// Shared gather core: fp32 accumulation over fp16 rows.
__device__ __forceinline__ float4 gather_node(const uint2* __restrict__ xin,
                                              int node, int lane) {
    int beg = __ldg(&g_rowptr[node]);
    int end = __ldg(&g_rowptr[node + 1]);
    float4 a = make_float4(0.f, 0.f, 0.f, 0.f);
    int i = beg;
    for (; i + 4 <= end; i += 4) {
        int2 e0 = __ldg(&g_csr[i + 0]);
        int2 e1 = __ldg(&g_csr[i + 1]);
        int2 e2 = __ldg(&g_csr[i + 2]);
        int2 e3 = __ldg(&g_csr[i + 3]);
        uint2 u0 = __ldg(&xin[e0.x * 32 + lane]);
        uint2 u1 = __ldg(&xin[e1.x * 32 + lane]);
        uint2 u2 = __ldg(&xin[e2.x * 32 + lane]);
        uint2 u3 = __ldg(&xin[e3.x * 32 + lane]);
        float w0 = __int_as_float(e0.y), w1 = __int_as_float(e1.y);
        float w2 = __int_as_float(e2.y), w3 = __int_as_float(e3.y);
        float4 v0 = h_to_f4(u0), v1 = h_to_f4(u1);
        float4 v2 = h_to_f4(u2), v3 = h_to_f4(u3);
        a.x += w0 * v0.x + w1 * v1.x + w2 * v2.x + w3 * v3.x;
        a.y += w0 * v0.y + w1 * v1.y + w2 * v2.y + w3 * v3.y;
        a.z += w0 * v0.z + w1 * v1.z + w2 * v2.z + w3 * v3.z;
        a.w += w0 * v0.w + w1 * v1.w + w2 * v2.w + w3 * v3.w;
    }
    for (; i < end; ++i) {
        int2 e = __ldg(&g_csr[i]);
        float w = __int_as_float(e.y);
        float4 v = h_to_f4(__ldg(&xin[e.x * 32 + lane]));
        a.x += w * v.x; a.y += w * v.y; a.z += w * v.z; a.w += w * v.w;
    }
    return a;
}

// Layers 1 & 2: gather -> write fp16. Buffers selected in DEVICE code.
// layer==1: e0h -> e1h ; layer==2: e1h -> e2h
__global__ void __launch_bounds__(256) k_prop12(int layer) {
    int gtid = blockIdx.x * blockDim.x + threadIdx.x;
    int node = gtid >> 5;
    if (node >= N_NODES) return;
    int lane = threadIdx.x & 31;

    const uint2* xin  = (layer == 1) ? g_e0h : g_e1h;
    uint2*       xout = (layer == 1) ? g_e1h : g_e2h;

    float4 a = gather_node(xin, node, lane);
    xout[node * 32 + lane] = f4_to_h(a);
}

// Layer 3 fused with final reduction:
// out = (e0_fp32 + e1 + e2 + conv(e2)) / 16, split into [int | geo] sections.
__global__ void __launch_bounds__(256) k_prop3(
    const float4* __restrict__ ui, const float4* __restrict__ ii,
    const float4* __restrict__ ug, const float4* __restrict__ ig,
    float4* __restrict__ out)
{
    int gtid = blockIdx.x * blockDim.x + threadIdx.x;
    int node = gtid >> 5;
    if (node >= N_NODES) return;
    int lane = threadIdx.x & 31;

    float4 a = gather_node(g_e2h, node, lane);           // layer-3 output

    float4 base = load_input_chunk(ui, ii, ug, ig, node, lane);  // e0 (fp32)
    float4 v1 = h_to_f4(__ldg(&g_e1h[node * 32 + lane]));
    float4 v2 = h_to_f4(__ldg(&g_e2h[node * 32 + lane]));

    const float s = 1.0f / 16.0f;
    float4 r;
    r.x = (base.x + v1.x + v2.x + a.x) * s;
    r.y = (base.y + v1.y + v2.y + a.y) * s;
    r.z = (base.z + v1.z + v2.z + a.z) * s;
    r.w = (base.w + v1.w + v2.w + a.w) * s;

    // Output: int section [N,64] then geo section [N,64] (float4 granules).
    const int geo_base = N_NODES * 16;
    if (lane < 16) out[node * 16 + lane] = r;
    else           out[geo_base + node * 16 + (lane - 16)] = r;
}

// ---------------------------------------------------------------------------
extern "C" void kernel_launch(void* const* d_in, const int* in_sizes, int n_in,
                              void* d_out, int out_size) {
    const float4* user_int = (const float4*)d_in[0];
    const float4* item_int = (const float4*)d_in[1];
    const float4* user_geo = (const float4*)d_in[2];
    const float4* item_geo = (const float4*)d_in[3];
    const int*    edge     = (const int*)d_in[4];
    const int* src = edge;        // row 0 of [2, E]
    const int* dst = edge + NE;   // row 1

    float4* out = (float4*)d_out;

    const int TB = 256;
    const int prop_blocks = (N_NODES * 32 + TB - 1) / TB;   // 25000

    k_zero<<<512, TB>>>();
    k_count<<<4096, TB>>>(dst);
    k_scan<<<1, 1024>>>();
    k_scatter<<<4096, TB>>>(src, dst);
    k_pack<<<prop_blocks, TB>>>(user_int, item_int, user_geo, item_geo);

    k_prop12<<<prop_blocks, TB>>>(1);   // layer 1: e0h -> e1h
    k_prop12<<<prop_blocks, TB>>>(2);   // layer 2: e1h -> e2h
    k_prop3<<<prop_blocks, TB>>>(user_int, item_int, user_geo, item_geo, out);
}